// round 1
// baseline (speedup 1.0000x reference)
#include <cuda_runtime.h>

#define DIM     2048
#define NE      64
#define TOPK    8
#define MAXT    (4 * 8192)

// ---- GEMM tiling ----
#define BT      128        // tokens per CTA
#define KC      16         // k-chunk per stage
#define NTHR    256
#define XSTR    132        // padded smem stride for x tile (128 tokens + 4 pad)
#define WSTR    68         // padded smem stride for w tile (64 experts + 4 pad)
#define NSTAGE  (DIM / KC) // 128

// Scratch (no cudaMalloc allowed): scores [T, 64] and histogram.
__device__ float g_scores[MAXT * NE];
__device__ int   g_hist[NE];

__device__ __forceinline__ void ffma2(unsigned long long &d,
                                      unsigned long long a,
                                      unsigned long long b) {
    // Blackwell packed 2x fp32 FMA (FFMA2) — only reachable via PTX f32x2.
    asm("fma.rn.f32x2 %0, %1, %2, %0;" : "+l"(d) : "l"(a), "l"(b));
}

__device__ __forceinline__ unsigned long long dup2(float w) {
    unsigned long long r;
    asm("mov.b64 %0, {%1, %1};" : "=l"(r) : "f"(w));
    return r;
}

__device__ __forceinline__ float2 ull_as_f2(unsigned long long v) {
    float2 r;
    asm("mov.b64 {%0, %1}, %2;" : "=f"(r.x), "=f"(r.y) : "l"(v));
    return r;
}

// ============================================================
// Kernel 1: scores[t][e] = dot(x[t], gw[e])
// CTA: 128 tokens x 64 experts, 256 threads.
// Thread tile: 4 tokens x 8 experts, accumulated as f32x2 token pairs.
// ============================================================
__global__ __launch_bounds__(NTHR, 2)
void gemm_kernel(const float* __restrict__ x,
                 const float* __restrict__ gw) {
    __shared__ float xs[2][KC][XSTR];
    __shared__ float ws[2][KC][WSTR];

    const int tid = threadIdx.x;
    const long long tb = (long long)blockIdx.x * BT;

    // Global-load indices: x tile = 128 tok x 16 k = 512 float4 -> 2/thread
    const int xch = tid & 3;        // float4 chunk within k-chunk (0..3)
    const int xtr = tid >> 2;       // token 0..63 (also +64)
    // w tile = 64 exp x 16 k = 256 float4 -> 1/thread
    const int wch = tid & 3;
    const int we  = tid >> 2;       // expert 0..63

    // Compute indices
    const int col = tid & 7;        // experts col*8 .. col*8+7
    const int row = tid >> 3;       // tokens  row*4 .. row*4+3

    unsigned long long accA[8], accB[8];
    #pragma unroll
    for (int e = 0; e < 8; e++) { accA[e] = 0ull; accB[e] = 0ull; }

    const float* xp0 = x + (tb + xtr) * DIM + xch * 4;
    const float* xp1 = x + (tb + xtr + 64) * DIM + xch * 4;
    const float* wp  = gw + (long long)we * DIM + wch * 4;

    float4 xv0 = *(const float4*)(xp0);
    float4 xv1 = *(const float4*)(xp1);
    float4 wv  = *(const float4*)(wp);

    for (int s = 0; s < NSTAGE; s++) {
        const int buf = s & 1;

        // Stage regs -> smem (padded strides: <=2-way STS conflicts)
        {
            float xa[4] = {xv0.x, xv0.y, xv0.z, xv0.w};
            float xb[4] = {xv1.x, xv1.y, xv1.z, xv1.w};
            float wa[4] = {wv.x,  wv.y,  wv.z,  wv.w};
            #pragma unroll
            for (int j = 0; j < 4; j++) {
                xs[buf][xch * 4 + j][xtr]      = xa[j];
                xs[buf][xch * 4 + j][xtr + 64] = xb[j];
                ws[buf][wch * 4 + j][we]       = wa[j];
            }
        }

        // Prefetch next stage (latency hidden behind compute)
        if (s + 1 < NSTAGE) {
            const int k0 = (s + 1) * KC;
            xv0 = *(const float4*)(xp0 + k0);
            xv1 = *(const float4*)(xp1 + k0);
            wv  = *(const float4*)(wp  + k0);
        }

        __syncthreads();

        #pragma unroll
        for (int kk = 0; kk < KC; kk++) {
            unsigned long long x01 =
                *(const unsigned long long*)&xs[buf][kk][row * 4];
            unsigned long long x23 =
                *(const unsigned long long*)&xs[buf][kk][row * 4 + 2];
            float4 w0 = *(const float4*)&ws[buf][kk][col * 8];
            float4 w1 = *(const float4*)&ws[buf][kk][col * 8 + 4];
            float wf[8] = {w0.x, w0.y, w0.z, w0.w, w1.x, w1.y, w1.z, w1.w};
            #pragma unroll
            for (int e = 0; e < 8; e++) {
                unsigned long long wd = dup2(wf[e]);
                ffma2(accA[e], x01, wd);
                ffma2(accB[e], x23, wd);
            }
        }
        // Single barrier per stage: buf[s&1] is next written at stage s+2,
        // which is after stage s+1's barrier -> all stage-s readers done.
        __syncthreads();
    }

    // Epilogue: 4 tokens x 8 experts -> g_scores
    float2 a[8], b[8];
    #pragma unroll
    for (int e = 0; e < 8; e++) { a[e] = ull_as_f2(accA[e]); b[e] = ull_as_f2(accB[e]); }

    float* base = g_scores + (tb + row * 4) * NE + col * 8;
    *(float4*)(base)              = make_float4(a[0].x, a[1].x, a[2].x, a[3].x);
    *(float4*)(base + 4)          = make_float4(a[4].x, a[5].x, a[6].x, a[7].x);
    *(float4*)(base + NE)         = make_float4(a[0].y, a[1].y, a[2].y, a[3].y);
    *(float4*)(base + NE + 4)     = make_float4(a[4].y, a[5].y, a[6].y, a[7].y);
    *(float4*)(base + 2 * NE)     = make_float4(b[0].x, b[1].x, b[2].x, b[3].x);
    *(float4*)(base + 2 * NE + 4) = make_float4(b[4].x, b[5].x, b[6].x, b[7].x);
    *(float4*)(base + 3 * NE)     = make_float4(b[0].y, b[1].y, b[2].y, b[3].y);
    *(float4*)(base + 3 * NE + 4) = make_float4(b[4].y, b[5].y, b[6].y, b[7].y);
}

// ============================================================
// Kernel 2: zero histogram
// ============================================================
__global__ void hist_zero_kernel() {
    g_hist[threadIdx.x] = 0;
}

// ============================================================
// Kernel 3: per-token softmax + top-8 + histogram.
// One warp per token; lane holds experts {lane, lane+32}.
// Tie-break: lower expert index wins (matches jax.lax.top_k).
// ============================================================
__global__ __launch_bounds__(256)
void topk_kernel(const float* __restrict__ bias,
                 float* __restrict__ out_w,
                 float* __restrict__ out_idx,
                 int T) {
    __shared__ int hist[NE];
    const int lane = threadIdx.x & 31;
    const int wid  = threadIdx.x >> 5;
    const int t    = blockIdx.x * 8 + wid;

    if (threadIdx.x < NE) hist[threadIdx.x] = 0;
    __syncthreads();

    if (t < T) {
        float s0 = g_scores[(long long)t * NE + lane]      + bias[lane];
        float s1 = g_scores[(long long)t * NE + 32 + lane] + bias[lane + 32];

        // max over 64
        float m = fmaxf(s0, s1);
        #pragma unroll
        for (int off = 16; off > 0; off >>= 1)
            m = fmaxf(m, __shfl_xor_sync(0xffffffffu, m, off));

        // softmax denominator over all 64
        float z = expf(s0 - m) + expf(s1 - m);
        #pragma unroll
        for (int off = 16; off > 0; off >>= 1)
            z += __shfl_xor_sync(0xffffffffu, z, off);
        float invz = 1.0f / z;

        // iterative top-8 extraction
        float v0 = s0, v1 = s1;
        float ts = 0.0f, myp = 0.0f;
        int   myi = 0;
        #pragma unroll
        for (int it = 0; it < TOPK; it++) {
            float cv; int ci;
            if (v0 >= v1) { cv = v0; ci = lane; }
            else          { cv = v1; ci = lane + 32; }
            #pragma unroll
            for (int off = 16; off > 0; off >>= 1) {
                float ov = __shfl_xor_sync(0xffffffffu, cv, off);
                int   oi = __shfl_xor_sync(0xffffffffu, ci, off);
                if (ov > cv || (ov == cv && oi < ci)) { cv = ov; ci = oi; }
            }
            float pv = expf(cv - m) * invz;
            ts += pv;
            if (lane == it) { myp = pv; myi = ci; }
            if (ci == lane)       v0 = -3.4e38f;
            if (ci == lane + 32)  v1 = -3.4e38f;
        }

        float w = myp / (ts + 1e-8f);
        if (lane < TOPK) {
            out_w[(long long)t * TOPK + lane]   = w;
            out_idx[(long long)t * TOPK + lane] = (float)myi;
            atomicAdd(&hist[myi], 1);
        }
    }

    __syncthreads();
    if (threadIdx.x < NE) atomicAdd(&g_hist[threadIdx.x], hist[threadIdx.x]);
}

// ============================================================
// Kernel 4: bias / EMA updates
// ============================================================
__global__ void finalize_kernel(const float* __restrict__ bias,
                                const float* __restrict__ usage_in,
                                float* __restrict__ out_bias,
                                float* __restrict__ out_usage,
                                float inv_total) {
    const int e = threadIdx.x;
    float u = (float)g_hist[e] * inv_total;
    out_bias[e]  = bias[e] - 0.01f * (u - 1.0f / (float)NE);
    out_usage[e] = 0.9f * usage_in[e] + 0.1f * u;
}

// ============================================================
extern "C" void kernel_launch(void* const* d_in, const int* in_sizes, int n_in,
                              void* d_out, int out_size) {
    const float* x     = (const float*)d_in[0];  // [4, 8192, 2048] f32
    const float* gw    = (const float*)d_in[1];  // [64, 2048] f32
    const float* bias  = (const float*)d_in[2];  // [64] f32
    const float* usage = (const float*)d_in[3];  // [64] f32

    const int T = in_sizes[0] / DIM;             // 32768

    float* out       = (float*)d_out;
    float* out_w     = out;                      // [T, 8]
    float* out_idx   = out + (long long)T * TOPK;// [T, 8] (as float)
    float* out_bias  = out + 2LL * T * TOPK;     // [64]
    float* out_usage = out_bias + NE;            // [64]

    gemm_kernel<<<T / BT, NTHR>>>(x, gw);
    hist_zero_kernel<<<1, NE>>>();
    topk_kernel<<<(T + 7) / 8, 256>>>(bias, out_w, out_idx, T);
    finalize_kernel<<<1, NE>>>(bias, usage, out_bias, out_usage,
                               1.0f / (float)(T * TOPK));
}